// round 12
// baseline (speedup 1.0000x reference)
#include <cuda_runtime.h>
#include <cuda_bf16.h>
#include <math.h>
#include <stdint.h>

// ---------------- problem constants ----------------
#define Dm   768
#define Hh   12
#define NL   12
#define FFd  3072
#define Bb   4
#define Tt   1024
#define Mrows (Bb*Tt)          // 4096
#define ATT_SCALE 0.03608439182435161f   // 768^-0.5
#define LN_EPS 1e-5f

// ---------------- scratch (no cudaMalloc allowed) ----------------
__device__ float g_x   [(size_t)Mrows*Dm];
__device__ float g_skip[(size_t)Mrows*Dm];

__device__ __nv_bfloat16 g_hh [(size_t)Mrows*Dm],  g_hl [(size_t)Mrows*Dm];
__device__ __nv_bfloat16 g_qh [(size_t)Mrows*Dm],  g_ql [(size_t)Mrows*Dm];
__device__ __nv_bfloat16 g_vh [(size_t)Mrows*Dm],  g_vl [(size_t)Mrows*Dm];
__device__ __nv_bfloat16 g_cxh[(size_t)Mrows*Dm],  g_cxl[(size_t)Mrows*Dm];
__device__ __nv_bfloat16 g_ffh[(size_t)Mrows*FFd], g_ffl[(size_t)Mrows*FFd];

// transposed + hi/lo-split weights: [L][N][K] bf16
__device__ __nv_bfloat16 g_wqh[(size_t)NL*Dm*Dm],  g_wql[(size_t)NL*Dm*Dm];
__device__ __nv_bfloat16 g_wvh[(size_t)NL*Dm*Dm],  g_wvl[(size_t)NL*Dm*Dm];
__device__ __nv_bfloat16 g_woh[(size_t)NL*Dm*Dm],  g_wol[(size_t)NL*Dm*Dm];
__device__ __nv_bfloat16 g_w1h[(size_t)NL*Dm*FFd], g_w1l[(size_t)NL*Dm*FFd];
__device__ __nv_bfloat16 g_w2h[(size_t)NL*Dm*FFd], g_w2l[(size_t)NL*Dm*FFd];

// ---------------- PTX helpers (arch-generic: sm_80 features only) ----------------
__device__ __forceinline__ uint32_t smem_u32(const void* p) {
    uint32_t a;
    asm("{ .reg .u64 t; cvta.to.shared.u64 t, %1; cvt.u32.u64 %0, t; }" : "=r"(a) : "l"(p));
    return a;
}
__device__ __forceinline__ void cp16(uint32_t s, const void* g) {
    asm volatile("cp.async.cg.shared.global [%0], [%1], 16;" :: "r"(s), "l"(g) : "memory");
}
__device__ __forceinline__ void cp_commit() { asm volatile("cp.async.commit_group;" ::: "memory"); }
template <int N> __device__ __forceinline__ void cp_wait() {
    asm volatile("cp.async.wait_group %0;" :: "n"(N) : "memory");
}
__device__ __forceinline__ void ldsm4(uint32_t* r, uint32_t addr) {
    asm volatile("ldmatrix.sync.aligned.m8n8.x4.shared.b16 {%0,%1,%2,%3}, [%4];"
        : "=r"(r[0]), "=r"(r[1]), "=r"(r[2]), "=r"(r[3]) : "r"(addr));
}
__device__ __forceinline__ void ldsm4t(uint32_t* r, uint32_t addr) {
    asm volatile("ldmatrix.sync.aligned.m8n8.x4.trans.shared.b16 {%0,%1,%2,%3}, [%4];"
        : "=r"(r[0]), "=r"(r[1]), "=r"(r[2]), "=r"(r[3]) : "r"(addr));
}
__device__ __forceinline__ void mma_bf16(float* c, const uint32_t* a, const uint32_t* b) {
    asm volatile("mma.sync.aligned.m16n8k16.row.col.f32.bf16.bf16.f32 "
        "{%0,%1,%2,%3}, {%4,%5,%6,%7}, {%8,%9}, {%0,%1,%2,%3};"
        : "+f"(c[0]), "+f"(c[1]), "+f"(c[2]), "+f"(c[3])
        : "r"(a[0]), "r"(a[1]), "r"(a[2]), "r"(a[3]), "r"(b[0]), "r"(b[1]));
}
__device__ __forceinline__ uint32_t packbf(float lo, float hi) {
    uint32_t d;
    asm("cvt.rn.bf16x2.f32 %0, %1, %2;" : "=r"(d) : "f"(hi), "f"(lo));
    return d;
}
__device__ __forceinline__ float bhi(float x) {
    return __bfloat162float(__float2bfloat16(x));
}

// ---------------- fused weight transpose + hi/lo split (ONE launch) ----------------
__global__ void wconv_all(const float* __restrict__ Wq, const float* __restrict__ Wv,
                          const float* __restrict__ Wo, const float* __restrict__ W1,
                          const float* __restrict__ W2,
                          __nv_bfloat16* qh, __nv_bfloat16* ql,
                          __nv_bfloat16* vh, __nv_bfloat16* vl,
                          __nv_bfloat16* oh, __nv_bfloat16* ol,
                          __nv_bfloat16* h1, __nv_bfloat16* l1,
                          __nv_bfloat16* h2, __nv_bfloat16* l2)
{
    __shared__ float t[32][33];
    int ti = blockIdx.x;
    const int l = blockIdx.y;
    const float* W; __nv_bfloat16 *Th, *Tl; int K, N;
    if (ti < 576)       { W = Wq; Th = qh; Tl = ql; K = Dm;  N = Dm;  }
    else if (ti < 1152) { W = Wv; Th = vh; Tl = vl; K = Dm;  N = Dm;  ti -= 576; }
    else if (ti < 1728) { W = Wo; Th = oh; Tl = ol; K = Dm;  N = Dm;  ti -= 1152; }
    else if (ti < 4032) { W = W1; Th = h1; Tl = l1; K = Dm;  N = FFd; ti -= 1728; }
    else                { W = W2; Th = h2; Tl = l2; K = FFd; N = Dm;  ti -= 4032; }

    const int nb = N / 32;
    const int n0 = (ti % nb) * 32, k0 = (ti / nb) * 32;
    const float* w = W + (size_t)l * K * N;
    __nv_bfloat16* th = Th + (size_t)l * K * N;
    __nv_bfloat16* tl = Tl + (size_t)l * K * N;
    const int tx = threadIdx.x, ty = threadIdx.y;
#pragma unroll
    for (int i = ty; i < 32; i += 8)
        t[i][tx] = w[(size_t)(k0 + i) * N + n0 + tx];
    __syncthreads();
#pragma unroll
    for (int i = ty; i < 32; i += 8) {
        float v = t[tx][i];
        __nv_bfloat16 hi = __float2bfloat16(v);
        __nv_bfloat16 lo = __float2bfloat16(v - __bfloat162float(hi));
        th[(size_t)(n0 + i) * K + k0 + tx] = hi;
        tl[(size_t)(n0 + i) * K + k0 + tx] = lo;
    }
}

// ---------------- layernorm (fp32 in -> bf16 hi/lo out) ----------------
__device__ __forceinline__ float block_sum(float v, float* red)
{
    int lane = threadIdx.x & 31, w = threadIdx.x >> 5;
#pragma unroll
    for (int o = 16; o; o >>= 1) v += __shfl_xor_sync(0xffffffffu, v, o);
    if (lane == 0) red[w] = v;
    __syncthreads();
    if (w == 0) {
        v = (lane < 8) ? red[lane] : 0.f;
#pragma unroll
        for (int o = 4; o; o >>= 1) v += __shfl_xor_sync(0xffffffffu, v, o);
        if (lane == 0) red[0] = v;
    }
    __syncthreads();
    float r = red[0];
    __syncthreads();
    return r;
}

__global__ void ln_kernel(const float* __restrict__ X, const float* __restrict__ g,
                          const float* __restrict__ bta,
                          __nv_bfloat16* __restrict__ Yh, __nv_bfloat16* __restrict__ Yl)
{
    __shared__ float red[32];
    const int row = blockIdx.x;
    const float* x = X + (size_t)row * Dm;
    const int t = threadIdx.x;
    float v0 = x[t], v1 = x[t + 256], v2 = x[t + 512];
    float mu = block_sum(v0 + v1 + v2, red) * (1.f / 768.f);
    float d0 = v0 - mu, d1 = v1 - mu, d2 = v2 - mu;
    float var = block_sum(d0*d0 + d1*d1 + d2*d2, red) * (1.f / 768.f);
    float rs = rsqrtf(var + LN_EPS);
    __nv_bfloat16* yh = Yh + (size_t)row * Dm;
    __nv_bfloat16* yl = Yl + (size_t)row * Dm;
#pragma unroll
    for (int p = 0; p < 3; p++) {
        int c = t + p * 256;
        float d = (p == 0) ? d0 : (p == 1) ? d1 : d2;
        float y = d * rs * g[c] + bta[c];
        __nv_bfloat16 hi = __float2bfloat16(y);
        yh[c] = hi;
        yl[c] = __float2bfloat16(y - __bfloat162float(hi));
    }
}

// ---------------- warp-MMA split-bf16 GEMM body (BM=128, BN=64, BK=32, 3 stages) ----------------
// 256 threads, 8 warps, warp tile 32x32. 2 CTAs/SM. One barrier per K-iteration.
// Inner loop issues MMAs term-outermost (hh x8, hl x8, lh x8) so the same
// accumulator is revisited at distance 8 (vs 2) -> hides HMMA accumulation RAW.
// Per-accumulator term order stays hh -> hl -> lh (bit-identical results).
// EPI: 1 = bias + residual -> fp32 ; 2 = bias + GELU -> bf16 hi/lo
//      3 = (bias + acc) * oscale -> bf16 hi/lo
#define AROW 80
#define ATILEB (128 * AROW)                // 10240
#define BTILEB (64 * AROW)                 // 5120
#define STAGEB (2 * ATILEB + 2 * BTILEB)   // 30720
#define NSTAGE 3
#define SMEM_GEMM_BYTES (NSTAGE * STAGEB + 512)

template <int EPI>
__device__ __forceinline__ void
gemm_body(int bm, int bn,
          const __nv_bfloat16* __restrict__ Ah, const __nv_bfloat16* __restrict__ Al,
          const __nv_bfloat16* __restrict__ Bh, const __nv_bfloat16* __restrict__ Bl,
          const float* __restrict__ bias, const float* __restrict__ Res,
          float* __restrict__ C, __nv_bfloat16* __restrict__ Ch, __nv_bfloat16* __restrict__ Cl,
          int N, int K, float oscale)
{
    extern __shared__ char smem_raw[];
    const uint32_t sb = (smem_u32(smem_raw) + 255) & ~255u;

    const int tid  = threadIdx.x;
    const int wid  = tid >> 5;
    const int lane = tid & 31;

    // A loads: 2 threads/row, 2 chunks each; B loads: 4 threads/row, 1 chunk each
    const int arow = tid >> 1;
    const int ac0  = (tid & 1) * 2;
    const int brow = tid >> 2;
    const int bch  = tid & 3;
    const uint32_t sArow = (uint32_t)arow * AROW;
    const uint32_t sBrow = (uint32_t)brow * AROW;
    const __nv_bfloat16* gA_h = Ah + (size_t)(bm + arow) * K;
    const __nv_bfloat16* gA_l = Al + (size_t)(bm + arow) * K;
    const __nv_bfloat16* gB_h = Bh + (size_t)(bn + brow) * K;
    const __nv_bfloat16* gB_l = Bl + (size_t)(bn + brow) * K;

    const int m0 = (wid >> 1) * 32;
    const int n0 = (wid & 1) * 32;

    const uint32_t aL = (uint32_t)(m0 + (lane & 15)) * AROW + (lane >> 4) * 16;
    const uint32_t bL = (uint32_t)(n0 + (lane & 7) + ((lane >> 4) & 1) * 8) * AROW
                        + ((lane >> 3) & 1) * 16;

    float acc[2][4][4];
#pragma unroll
    for (int mi = 0; mi < 2; mi++)
#pragma unroll
        for (int nj = 0; nj < 4; nj++)
#pragma unroll
            for (int k = 0; k < 4; k++) acc[mi][nj][k] = 0.f;

    const int NIT = K >> 5;

    // prologue: stages 0 and 1
#pragma unroll
    for (int st = 0; st < 2; st++) {
        const uint32_t tb = sb + st * STAGEB;
        const int k0 = st << 5;
#pragma unroll
        for (int s = 0; s < 2; s++) {
            const int ch = ac0 + s;
            cp16(tb + 0 * ATILEB + sArow + ch * 16, gA_h + k0 + ch * 8);
            cp16(tb + 1 * ATILEB + sArow + ch * 16, gA_l + k0 + ch * 8);
        }
        cp16(tb + 2 * ATILEB + sBrow + bch * 16,          gB_h + k0 + bch * 8);
        cp16(tb + 2 * ATILEB + BTILEB + sBrow + bch * 16, gB_l + k0 + bch * 8);
        cp_commit();
    }

    int buf = 0, nbuf = 2;
    for (int it = 0; it < NIT; it++) {
        if (it + 1 < NIT) cp_wait<1>(); else cp_wait<0>();
        __syncthreads();   // one barrier per iteration

        if (it + 2 < NIT) {
            const uint32_t tb = sb + nbuf * STAGEB;
            const int k0 = (it + 2) << 5;
#pragma unroll
            for (int s = 0; s < 2; s++) {
                const int ch = ac0 + s;
                cp16(tb + 0 * ATILEB + sArow + ch * 16, gA_h + k0 + ch * 8);
                cp16(tb + 1 * ATILEB + sArow + ch * 16, gA_l + k0 + ch * 8);
            }
            cp16(tb + 2 * ATILEB + sBrow + bch * 16,          gB_h + k0 + bch * 8);
            cp16(tb + 2 * ATILEB + BTILEB + sBrow + bch * 16, gB_l + k0 + bch * 8);
            cp_commit();
        }

        const uint32_t tb = sb + buf * STAGEB;

#pragma unroll
        for (int kk = 0; kk < 2; kk++) {
            uint32_t ah[2][4], al[2][4], bh4[2][4], bl4[2][4];
#pragma unroll
            for (int mi = 0; mi < 2; mi++) {
                ldsm4(ah[mi], tb + 0 * ATILEB + aL + mi * (16 * AROW) + kk * 32);
                ldsm4(al[mi], tb + 1 * ATILEB + aL + mi * (16 * AROW) + kk * 32);
            }
#pragma unroll
            for (int np = 0; np < 2; np++) {
                ldsm4(bh4[np], tb + 2 * ATILEB + bL + (uint32_t)np * (16 * AROW) + kk * 32);
                ldsm4(bl4[np], tb + 2 * ATILEB + BTILEB + bL + (uint32_t)np * (16 * AROW) + kk * 32);
            }
            // term 1: ah x bh (8 independent accumulators back-to-back)
#pragma unroll
            for (int np = 0; np < 2; np++)
#pragma unroll
                for (int mi = 0; mi < 2; mi++) {
                    mma_bf16(acc[mi][2*np],     ah[mi], &bh4[np][0]);
                    mma_bf16(acc[mi][2*np + 1], ah[mi], &bh4[np][2]);
                }
            // term 2: ah x bl
#pragma unroll
            for (int np = 0; np < 2; np++)
#pragma unroll
                for (int mi = 0; mi < 2; mi++) {
                    mma_bf16(acc[mi][2*np],     ah[mi], &bl4[np][0]);
                    mma_bf16(acc[mi][2*np + 1], ah[mi], &bl4[np][2]);
                }
            // term 3: al x bh
#pragma unroll
            for (int np = 0; np < 2; np++)
#pragma unroll
                for (int mi = 0; mi < 2; mi++) {
                    mma_bf16(acc[mi][2*np],     al[mi], &bh4[np][0]);
                    mma_bf16(acc[mi][2*np + 1], al[mi], &bh4[np][2]);
                }
        }

        buf  = (buf == NSTAGE - 1)  ? 0 : buf + 1;
        nbuf = (nbuf == NSTAGE - 1) ? 0 : nbuf + 1;
    }

    const int g = lane >> 2, t4 = lane & 3;
#pragma unroll
    for (int mi = 0; mi < 2; mi++) {
#pragma unroll
        for (int half = 0; half < 2; half++) {
            const int row = bm + m0 + mi * 16 + g + half * 8;
#pragma unroll
            for (int nj = 0; nj < 4; nj++) {
                const int col = bn + n0 + nj * 8 + 2 * t4;
                float v0 = acc[mi][nj][2 * half]     + bias[col];
                float v1 = acc[mi][nj][2 * half + 1] + bias[col + 1];
                if (EPI == 1) {
                    const float2 rr = *(const float2*)&Res[(size_t)row * N + col];
                    v0 += rr.x; v1 += rr.y;
                }
                if (EPI == 2) {
                    v0 = 0.5f * v0 * (1.0f + erff(v0 * 0.70710678118654752f));
                    v1 = 0.5f * v1 * (1.0f + erff(v1 * 0.70710678118654752f));
                }
                if (EPI == 3) { v0 *= oscale; v1 *= oscale; }
                if (EPI == 2 || EPI == 3) {
                    __nv_bfloat16 h0 = __float2bfloat16(v0);
                    __nv_bfloat16 h1 = __float2bfloat16(v1);
                    __nv_bfloat16 l0 = __float2bfloat16(v0 - __bfloat162float(h0));
                    __nv_bfloat16 l1 = __float2bfloat16(v1 - __bfloat162float(h1));
                    *(__nv_bfloat162*)&Ch[(size_t)row * N + col] = __nv_bfloat162(h0, h1);
                    *(__nv_bfloat162*)&Cl[(size_t)row * N + col] = __nv_bfloat162(l0, l1);
                } else {
                    *(float2*)&C[(size_t)row * N + col] = make_float2(v0, v1);
                }
            }
        }
    }
}

template <int EPI>
__global__ void __launch_bounds__(256, 2)
gemm_k(const __nv_bfloat16* __restrict__ Ah, const __nv_bfloat16* __restrict__ Al,
       const __nv_bfloat16* __restrict__ Bh, const __nv_bfloat16* __restrict__ Bl,
       const float* __restrict__ bias, const float* __restrict__ Res,
       float* __restrict__ C, __nv_bfloat16* __restrict__ Ch, __nv_bfloat16* __restrict__ Cl,
       int N, int K, float oscale)
{
    gemm_body<EPI>(blockIdx.y * 128, blockIdx.x * 64, Ah, Al, Bh, Bl,
                   bias, Res, C, Ch, Cl, N, K, oscale);
}

// fused Q+V projection: grid.x = 24 (12 Q cols, 12 V cols)
__global__ void __launch_bounds__(256, 2)
gemm_qv(const __nv_bfloat16* __restrict__ Ah, const __nv_bfloat16* __restrict__ Al,
        const __nv_bfloat16* __restrict__ Wqh, const __nv_bfloat16* __restrict__ Wql,
        const __nv_bfloat16* __restrict__ Wvh, const __nv_bfloat16* __restrict__ Wvl,
        const float* __restrict__ bq, const float* __restrict__ bv,
        __nv_bfloat16* __restrict__ Qh, __nv_bfloat16* __restrict__ Ql,
        __nv_bfloat16* __restrict__ Vh, __nv_bfloat16* __restrict__ Vl)
{
    const int bm = blockIdx.y * 128;
    const int xw = blockIdx.x;
    if (xw < Dm / 64)
        gemm_body<3>(bm, xw * 64, Ah, Al, Wqh, Wql, bq, nullptr,
                     nullptr, Qh, Ql, Dm, Dm, ATT_SCALE);
    else
        gemm_body<3>(bm, (xw - Dm / 64) * 64, Ah, Al, Wvh, Wvl, bv, nullptr,
                     nullptr, Vh, Vl, Dm, Dm, 1.0f);
}

// ---------------- tensor-core flash attention (scores = q . v) ----------------
#define AROWB 144
#define ATILE (64 * AROWB)                       // 9216
#define SMEM_ATTN_BYTES (6 * ATILE + 1024)

__global__ void __launch_bounds__(128, 1)
attn_mma(const __nv_bfloat16* __restrict__ Qh, const __nv_bfloat16* __restrict__ Ql,
         const __nv_bfloat16* __restrict__ Vh, const __nv_bfloat16* __restrict__ Vl,
         __nv_bfloat16* __restrict__ Oh, __nv_bfloat16* __restrict__ Ol)
{
    extern __shared__ char smem_raw[];
    const uint32_t sb = (smem_u32(smem_raw) + 255) & ~255u;
    const uint32_t sQh = sb, sQl = sb + ATILE;
    const uint32_t sV  = sb + 2 * ATILE;

    const int bh_ = blockIdx.y;
    const int b = bh_ / Hh, h = bh_ % Hh;
    const int l0 = blockIdx.x * 64;
    const int tid = threadIdx.x;
    const int wid = tid >> 5;
    const int lane = tid & 31;

    const int lrow = tid >> 1;
    const int cg   = (tid & 1) * 4;
    const uint32_t srow = (uint32_t)lrow * AROWB;

    const __nv_bfloat16* gq_h = Qh + (size_t)(b * Tt + l0 + lrow) * Dm + h * 64;
    const __nv_bfloat16* gq_l = Ql + (size_t)(b * Tt + l0 + lrow) * Dm + h * 64;

    {
#pragma unroll
        for (int s = 0; s < 4; s++) {
            const int ch = cg + s;
            cp16(sQh + srow + ch * 16, gq_h + ch * 8);
            cp16(sQl + srow + ch * 16, gq_l + ch * 8);
        }
        const __nv_bfloat16* gv_h = Vh + (size_t)(b * Tt + 0 + lrow) * Dm + h * 64;
        const __nv_bfloat16* gv_l = Vl + (size_t)(b * Tt + 0 + lrow) * Dm + h * 64;
#pragma unroll
        for (int s = 0; s < 4; s++) {
            const int ch = cg + s;
            cp16(sV + srow + ch * 16,         gv_h + ch * 8);
            cp16(sV + ATILE + srow + ch * 16, gv_l + ch * 8);
        }
        cp_commit();
    }

    uint32_t qa_h[4][4], qa_l[4][4];
    float o[8][4];
#pragma unroll
    for (int nj = 0; nj < 8; nj++)
#pragma unroll
        for (int k = 0; k < 4; k++) o[nj][k] = 0.f;
    float mrow0 = -1e30f, mrow1 = -1e30f, ls0 = 0.f, ls1 = 0.f;

    const uint32_t aL = (uint32_t)(wid * 16 + (lane & 15)) * AROWB + (lane >> 4) * 16;
    const uint32_t bL = (uint32_t)((lane & 7) + ((lane >> 4) & 1) * 8) * AROWB
                        + ((lane >> 3) & 1) * 16;
    const uint32_t tLrow = (uint32_t)((lane & 7) + ((lane >> 3) & 1) * 8);
    const uint32_t tLcol = ((lane >> 4) & 1) * 16;

    const int NT = Tt / 64;
    for (int it = 0; it < NT; it++) {
        const int buf = it & 1;

        if (it + 1 < NT) {
            const uint32_t dst = sV + (buf ^ 1) * 2 * ATILE;
            const __nv_bfloat16* gv_h = Vh + (size_t)(b * Tt + (it + 1) * 64 + lrow) * Dm + h * 64;
            const __nv_bfloat16* gv_l = Vl + (size_t)(b * Tt + (it + 1) * 64 + lrow) * Dm + h * 64;
#pragma unroll
            for (int s = 0; s < 4; s++) {
                const int ch = cg + s;
                cp16(dst + srow + ch * 16,         gv_h + ch * 8);
                cp16(dst + ATILE + srow + ch * 16, gv_l + ch * 8);
            }
            cp_commit();
            cp_wait<1>();
        } else {
            cp_wait<0>();
        }
        __syncthreads();

        if (it == 0) {
#pragma unroll
            for (int k = 0; k < 4; k++) {
                ldsm4(qa_h[k], sQh + aL + k * 32);
                ldsm4(qa_l[k], sQl + aL + k * 32);
            }
        }

        const uint32_t vb  = sV + buf * 2 * ATILE;
        const uint32_t vbl = vb + ATILE;

        float s[8][4];
#pragma unroll
        for (int nj = 0; nj < 8; nj++)
#pragma unroll
            for (int k = 0; k < 4; k++) s[nj][k] = 0.f;

#pragma unroll
        for (int kk = 0; kk < 4; kk++) {
#pragma unroll
            for (int nb = 0; nb < 4; nb++) {
                uint32_t bh4[4], bl4[4];
                ldsm4(bh4, vb  + bL + (uint32_t)nb * (16 * AROWB) + kk * 32);
                ldsm4(bl4, vbl + bL + (uint32_t)nb * (16 * AROWB) + kk * 32);
                mma_bf16(s[2*nb],     qa_h[kk], &bh4[0]);
                mma_bf16(s[2*nb + 1], qa_h[kk], &bh4[2]);
                mma_bf16(s[2*nb],     qa_h[kk], &bl4[0]);
                mma_bf16(s[2*nb + 1], qa_h[kk], &bl4[2]);
                mma_bf16(s[2*nb],     qa_l[kk], &bh4[0]);
                mma_bf16(s[2*nb + 1], qa_l[kk], &bh4[2]);
            }
        }

        float tmax0 = -1e30f, tmax1 = -1e30f;
#pragma unroll
        for (int nj = 0; nj < 8; nj++) {
            tmax0 = fmaxf(tmax0, fmaxf(s[nj][0], s[nj][1]));
            tmax1 = fmaxf(tmax1, fmaxf(s[nj][2], s[nj][3]));
        }
        tmax0 = fmaxf(tmax0, __shfl_xor_sync(0xffffffffu, tmax0, 1));
        tmax0 = fmaxf(tmax0, __shfl_xor_sync(0xffffffffu, tmax0, 2));
        tmax1 = fmaxf(tmax1, __shfl_xor_sync(0xffffffffu, tmax1, 1));
        tmax1 = fmaxf(tmax1, __shfl_xor_sync(0xffffffffu, tmax1, 2));

        const float mn0 = fmaxf(mrow0, tmax0), mn1 = fmaxf(mrow1, tmax1);
        const float c0 = __expf(mrow0 - mn0), c1 = __expf(mrow1 - mn1);
        mrow0 = mn0; mrow1 = mn1;

        float sum0 = 0.f, sum1 = 0.f;
#pragma unroll
        for (int nj = 0; nj < 8; nj++) {
            s[nj][0] = __expf(s[nj][0] - mn0); sum0 += s[nj][0];
            s[nj][1] = __expf(s[nj][1] - mn0); sum0 += s[nj][1];
            s[nj][2] = __expf(s[nj][2] - mn1); sum1 += s[nj][2];
            s[nj][3] = __expf(s[nj][3] - mn1); sum1 += s[nj][3];
        }
        sum0 += __shfl_xor_sync(0xffffffffu, sum0, 1);
        sum0 += __shfl_xor_sync(0xffffffffu, sum0, 2);
        sum1 += __shfl_xor_sync(0xffffffffu, sum1, 1);
        sum1 += __shfl_xor_sync(0xffffffffu, sum1, 2);
        ls0 = ls0 * c0 + sum0;
        ls1 = ls1 * c1 + sum1;

#pragma unroll
        for (int nj = 0; nj < 8; nj++) {
            o[nj][0] *= c0; o[nj][1] *= c0;
            o[nj][2] *= c1; o[nj][3] *= c1;
        }

        uint32_t pa_h[4][4], pa_l[4][4];
#pragma unroll
        for (int kb = 0; kb < 4; kb++) {
            const int f0 = 2 * kb, f1 = 2 * kb + 1;
            float ph[8], pl[8];
#pragma unroll
            for (int e = 0; e < 4; e++) {
                ph[e]     = bhi(s[f0][e]); pl[e]     = s[f0][e] - ph[e];
                ph[4 + e] = bhi(s[f1][e]); pl[4 + e] = s[f1][e] - ph[4 + e];
            }
            pa_h[kb][0] = packbf(ph[0], ph[1]); pa_h[kb][1] = packbf(ph[2], ph[3]);
            pa_h[kb][2] = packbf(ph[4], ph[5]); pa_h[kb][3] = packbf(ph[6], ph[7]);
            pa_l[kb][0] = packbf(pl[0], pl[1]); pa_l[kb][1] = packbf(pl[2], pl[3]);
            pa_l[kb][2] = packbf(pl[4], pl[5]); pa_l[kb][3] = packbf(pl[6], pl[7]);
        }

#pragma unroll
        for (int kb = 0; kb < 4; kb++) {
#pragma unroll
            for (int nb = 0; nb < 4; nb++) {
                const uint32_t ta = (uint32_t)(kb * 16 + tLrow) * AROWB
                                    + (uint32_t)nb * 32 + tLcol;
                uint32_t tvh[4], tvl[4];
                ldsm4t(tvh, vb  + ta);
                ldsm4t(tvl, vbl + ta);
                mma_bf16(o[2*nb],     pa_h[kb], &tvh[0]);
                mma_bf16(o[2*nb + 1], pa_h[kb], &tvh[2]);
                mma_bf16(o[2*nb],     pa_h[kb], &tvl[0]);
                mma_bf16(o[2*nb + 1], pa_h[kb], &tvl[2]);
                mma_bf16(o[2*nb],     pa_l[kb], &tvh[0]);
                mma_bf16(o[2*nb + 1], pa_l[kb], &tvh[2]);
            }
        }
        __syncthreads();
    }

    const float inv0 = 1.f / ls0, inv1 = 1.f / ls1;
    const int g = lane >> 2, t4 = lane & 3;
    const int row0 = b * Tt + l0 + wid * 16 + g;
    const int row1 = row0 + 8;
#pragma unroll
    for (int nj = 0; nj < 8; nj++) {
        const int col = h * 64 + nj * 8 + 2 * t4;
        float f0 = o[nj][0] * inv0, f1 = o[nj][1] * inv0;
        float f2 = o[nj][2] * inv1, f3 = o[nj][3] * inv1;
        __nv_bfloat16 h0 = __float2bfloat16(f0), h1 = __float2bfloat16(f1);
        __nv_bfloat16 h2 = __float2bfloat16(f2), h3 = __float2bfloat16(f3);
        *(__nv_bfloat162*)&Oh[(size_t)row0 * Dm + col] = __nv_bfloat162(h0, h1);
        *(__nv_bfloat162*)&Oh[(size_t)row1 * Dm + col] = __nv_bfloat162(h2, h3);
        *(__nv_bfloat162*)&Ol[(size_t)row0 * Dm + col] =
            __nv_bfloat162(__float2bfloat16(f0 - __bfloat162float(h0)),
                           __float2bfloat16(f1 - __bfloat162float(h1)));
        *(__nv_bfloat162*)&Ol[(size_t)row1 * Dm + col] =
            __nv_bfloat162(__float2bfloat16(f2 - __bfloat162float(h2)),
                           __float2bfloat16(f3 - __bfloat162float(h3)));
    }
}

// ---------------- host ----------------
extern "C" void kernel_launch(void* const* d_in, const int* in_sizes, int n_in,
                              void* d_out, int out_size)
{
    const float* x     = (const float*)d_in[0];
    const float* ln1_g = (const float*)d_in[1];
    const float* ln1_b = (const float*)d_in[2];
    const float* Wq    = (const float*)d_in[3];
    const float* bq    = (const float*)d_in[4];
    const float* Wv    = (const float*)d_in[5];
    const float* bv    = (const float*)d_in[6];
    const float* Wo    = (const float*)d_in[7];
    const float* bo    = (const float*)d_in[8];
    const float* ln2_g = (const float*)d_in[9];
    const float* ln2_b = (const float*)d_in[10];
    const float* W1    = (const float*)d_in[11];
    const float* b1    = (const float*)d_in[12];
    const float* W2    = (const float*)d_in[13];
    const float* b2    = (const float*)d_in[14];
    float* out = (float*)d_out;

    float *gx, *gskip;
    __nv_bfloat16 *hh, *hl, *qh, *ql, *vh, *vl, *cxh, *cxl, *ffh, *ffl;
    __nv_bfloat16 *wqh, *wql, *wvh, *wvl, *woh, *wol, *w1h, *w1l, *w2h, *w2l;
    cudaGetSymbolAddress((void**)&gx,    g_x);
    cudaGetSymbolAddress((void**)&gskip, g_skip);
    cudaGetSymbolAddress((void**)&hh,  g_hh);  cudaGetSymbolAddress((void**)&hl,  g_hl);
    cudaGetSymbolAddress((void**)&qh,  g_qh);  cudaGetSymbolAddress((void**)&ql,  g_ql);
    cudaGetSymbolAddress((void**)&vh,  g_vh);  cudaGetSymbolAddress((void**)&vl,  g_vl);
    cudaGetSymbolAddress((void**)&cxh, g_cxh); cudaGetSymbolAddress((void**)&cxl, g_cxl);
    cudaGetSymbolAddress((void**)&ffh, g_ffh); cudaGetSymbolAddress((void**)&ffl, g_ffl);
    cudaGetSymbolAddress((void**)&wqh, g_wqh); cudaGetSymbolAddress((void**)&wql, g_wql);
    cudaGetSymbolAddress((void**)&wvh, g_wvh); cudaGetSymbolAddress((void**)&wvl, g_wvl);
    cudaGetSymbolAddress((void**)&woh, g_woh); cudaGetSymbolAddress((void**)&wol, g_wol);
    cudaGetSymbolAddress((void**)&w1h, g_w1h); cudaGetSymbolAddress((void**)&w1l, g_w1l);
    cudaGetSymbolAddress((void**)&w2h, g_w2h); cudaGetSymbolAddress((void**)&w2l, g_w2l);

    cudaFuncSetAttribute(gemm_k<1>, cudaFuncAttributeMaxDynamicSharedMemorySize, SMEM_GEMM_BYTES);
    cudaFuncSetAttribute(gemm_k<2>, cudaFuncAttributeMaxDynamicSharedMemorySize, SMEM_GEMM_BYTES);
    cudaFuncSetAttribute(gemm_qv,   cudaFuncAttributeMaxDynamicSharedMemorySize, SMEM_GEMM_BYTES);
    cudaFuncSetAttribute(attn_mma,  cudaFuncAttributeMaxDynamicSharedMemorySize, SMEM_ATTN_BYTES);

    wconv_all<<<dim3(6336, NL), dim3(32, 8)>>>(Wq, Wv, Wo, W1, W2,
        wqh, wql, wvh, wvl, woh, wol, w1h, w1l, w2h, w2l);

    const dim3 gQV(2 * Dm / 64, Mrows / 128);  // (24, 32)
    const dim3 gD (Dm / 64,     Mrows / 128);  // (12, 32)
    const dim3 gF (FFd / 64,    Mrows / 128);  // (48, 32)
    const dim3 gA (Tt / 64, Bb * Hh);          // (16, 48)

    const float* cur = x;
    for (int l = 0; l < NL; l++) {
        float* nxt = (l == NL - 1) ? out : gx;
        const size_t oDD = (size_t)l * Dm * Dm;
        const size_t oDF = (size_t)l * Dm * FFd;
        const int lD = l * Dm, lFF = l * FFd;

        ln_kernel<<<Mrows, 256>>>(cur, ln1_g + lD, ln1_b + lD, hh, hl);
        gemm_qv<<<gQV, 256, SMEM_GEMM_BYTES>>>(hh, hl, wqh + oDD, wql + oDD,
            wvh + oDD, wvl + oDD, bq + lD, bv + lD, qh, ql, vh, vl);
        attn_mma<<<gA, 128, SMEM_ATTN_BYTES>>>(qh, ql, vh, vl, cxh, cxl);
        gemm_k<1><<<gD, 256, SMEM_GEMM_BYTES>>>(cxh, cxl, woh + oDD, wol + oDD,
            bo + lD, cur, gskip, nullptr, nullptr, Dm, Dm, 1.0f);
        ln_kernel<<<Mrows, 256>>>(gskip, ln2_g + lD, ln2_b + lD, hh, hl);
        gemm_k<2><<<gF, 256, SMEM_GEMM_BYTES>>>(hh, hl, w1h + oDF, w1l + oDF,
            b1 + lFF, nullptr, nullptr, ffh, ffl, FFd, Dm, 1.0f);
        gemm_k<1><<<gD, 256, SMEM_GEMM_BYTES>>>(ffh, ffl, w2h + oDF, w2l + oDF,
            b2 + lD, gskip, nxt, nullptr, nullptr, Dm, FFd, 1.0f);

        cur = nxt;
    }
}

// round 13
// speedup vs baseline: 2.1930x; 2.1930x over previous
#include <cuda_runtime.h>
#include <cuda_fp16.h>
#include <math.h>
#include <stdint.h>

// ---------------- problem constants ----------------
#define Dm   768
#define Hh   12
#define NL   12
#define FFd  3072
#define Bb   4
#define Tt   1024
#define Mrows (Bb*Tt)          // 4096
#define ATT_SCALE 0.03608439182435161f   // 768^-0.5
#define LN_EPS 1e-5f

// ---------------- scratch (no cudaMalloc allowed) ----------------
__device__ float g_x   [(size_t)Mrows*Dm];
__device__ float g_skip[(size_t)Mrows*Dm];

__device__ __half g_h  [(size_t)Mrows*Dm];
__device__ __half g_q  [(size_t)Mrows*Dm];
__device__ __half g_v  [(size_t)Mrows*Dm];
__device__ __half g_cx [(size_t)Mrows*Dm];
__device__ __half g_ff [(size_t)Mrows*FFd];

// transposed fp16 weights: [L][N][K]
__device__ __half g_wq[(size_t)NL*Dm*Dm];
__device__ __half g_wv[(size_t)NL*Dm*Dm];
__device__ __half g_wo[(size_t)NL*Dm*Dm];
__device__ __half g_w1[(size_t)NL*Dm*FFd];
__device__ __half g_w2[(size_t)NL*Dm*FFd];

// ---------------- PTX helpers (arch-generic: sm_80 features only) ----------------
__device__ __forceinline__ uint32_t smem_u32(const void* p) {
    uint32_t a;
    asm("{ .reg .u64 t; cvta.to.shared.u64 t, %1; cvt.u32.u64 %0, t; }" : "=r"(a) : "l"(p));
    return a;
}
__device__ __forceinline__ void cp16(uint32_t s, const void* g) {
    asm volatile("cp.async.cg.shared.global [%0], [%1], 16;" :: "r"(s), "l"(g) : "memory");
}
__device__ __forceinline__ void cp_commit() { asm volatile("cp.async.commit_group;" ::: "memory"); }
template <int N> __device__ __forceinline__ void cp_wait() {
    asm volatile("cp.async.wait_group %0;" :: "n"(N) : "memory");
}
__device__ __forceinline__ void ldsm4(uint32_t* r, uint32_t addr) {
    asm volatile("ldmatrix.sync.aligned.m8n8.x4.shared.b16 {%0,%1,%2,%3}, [%4];"
        : "=r"(r[0]), "=r"(r[1]), "=r"(r[2]), "=r"(r[3]) : "r"(addr));
}
__device__ __forceinline__ void ldsm4t(uint32_t* r, uint32_t addr) {
    asm volatile("ldmatrix.sync.aligned.m8n8.x4.trans.shared.b16 {%0,%1,%2,%3}, [%4];"
        : "=r"(r[0]), "=r"(r[1]), "=r"(r[2]), "=r"(r[3]) : "r"(addr));
}
__device__ __forceinline__ void mma_f16(float* c, const uint32_t* a, const uint32_t* b) {
    asm volatile("mma.sync.aligned.m16n8k16.row.col.f32.f16.f16.f32 "
        "{%0,%1,%2,%3}, {%4,%5,%6,%7}, {%8,%9}, {%0,%1,%2,%3};"
        : "+f"(c[0]), "+f"(c[1]), "+f"(c[2]), "+f"(c[3])
        : "r"(a[0]), "r"(a[1]), "r"(a[2]), "r"(a[3]), "r"(b[0]), "r"(b[1]));
}
__device__ __forceinline__ uint32_t packh2(float lo, float hi) {
    __half2 h = __floats2half2_rn(lo, hi);
    return *(uint32_t*)&h;
}

// ---------------- fused weight transpose + fp16 convert (ONE launch) ----------------
__global__ void wconv_all(const float* __restrict__ Wq, const float* __restrict__ Wv,
                          const float* __restrict__ Wo, const float* __restrict__ W1,
                          const float* __restrict__ W2,
                          __half* tq, __half* tv, __half* to_,
                          __half* t1, __half* t2)
{
    __shared__ float t[32][33];
    int ti = blockIdx.x;
    const int l = blockIdx.y;
    const float* W; __half* Th; int K, N;
    if (ti < 576)       { W = Wq; Th = tq;  K = Dm;  N = Dm;  }
    else if (ti < 1152) { W = Wv; Th = tv;  K = Dm;  N = Dm;  ti -= 576; }
    else if (ti < 1728) { W = Wo; Th = to_; K = Dm;  N = Dm;  ti -= 1152; }
    else if (ti < 4032) { W = W1; Th = t1;  K = Dm;  N = FFd; ti -= 1728; }
    else                { W = W2; Th = t2;  K = FFd; N = Dm;  ti -= 4032; }

    const int nb = N / 32;
    const int n0 = (ti % nb) * 32, k0 = (ti / nb) * 32;
    const float* w = W + (size_t)l * K * N;
    __half* th = Th + (size_t)l * K * N;
    const int tx = threadIdx.x, ty = threadIdx.y;
#pragma unroll
    for (int i = ty; i < 32; i += 8)
        t[i][tx] = w[(size_t)(k0 + i) * N + n0 + tx];
    __syncthreads();
#pragma unroll
    for (int i = ty; i < 32; i += 8)
        th[(size_t)(n0 + i) * K + k0 + tx] = __float2half(t[tx][i]);
}

// ---------------- layernorm (fp32 in -> fp16 out) ----------------
__device__ __forceinline__ float block_sum(float v, float* red)
{
    int lane = threadIdx.x & 31, w = threadIdx.x >> 5;
#pragma unroll
    for (int o = 16; o; o >>= 1) v += __shfl_xor_sync(0xffffffffu, v, o);
    if (lane == 0) red[w] = v;
    __syncthreads();
    if (w == 0) {
        v = (lane < 8) ? red[lane] : 0.f;
#pragma unroll
        for (int o = 4; o; o >>= 1) v += __shfl_xor_sync(0xffffffffu, v, o);
        if (lane == 0) red[0] = v;
    }
    __syncthreads();
    float r = red[0];
    __syncthreads();
    return r;
}

__global__ void ln_kernel(const float* __restrict__ X, const float* __restrict__ g,
                          const float* __restrict__ bta, __half* __restrict__ Y)
{
    __shared__ float red[32];
    const int row = blockIdx.x;
    const float* x = X + (size_t)row * Dm;
    const int t = threadIdx.x;
    float v0 = x[t], v1 = x[t + 256], v2 = x[t + 512];
    float mu = block_sum(v0 + v1 + v2, red) * (1.f / 768.f);
    float d0 = v0 - mu, d1 = v1 - mu, d2 = v2 - mu;
    float var = block_sum(d0*d0 + d1*d1 + d2*d2, red) * (1.f / 768.f);
    float rs = rsqrtf(var + LN_EPS);
    __half* y = Y + (size_t)row * Dm;
#pragma unroll
    for (int p = 0; p < 3; p++) {
        int c = t + p * 256;
        float d = (p == 0) ? d0 : (p == 1) ? d1 : d2;
        y[c] = __float2half(d * rs * g[c] + bta[c]);
    }
}

// ---------------- warp-MMA fp16 GEMM body (BM=128, BN=64, BK=32, 3 stages) ----------------
// 256 threads, 8 warps, warp tile 32x32. 3 CTAs/SM. One barrier per K-iteration.
// EPI: 1 = bias + residual -> fp32 ; 2 = bias + GELU -> fp16
//      3 = (bias + acc) * oscale -> fp16
#define AROW 80
#define ATILEB (128 * AROW)                // 10240
#define BTILEB (64 * AROW)                 // 5120
#define STAGEB (ATILEB + BTILEB)           // 15360
#define NSTAGE 3
#define SMEM_GEMM_BYTES (NSTAGE * STAGEB + 512)

template <int EPI>
__device__ __forceinline__ void
gemm_body(int bm, int bn,
          const __half* __restrict__ A, const __half* __restrict__ B,
          const float* __restrict__ bias, const float* __restrict__ Res,
          float* __restrict__ C, __half* __restrict__ Ch,
          int N, int K, float oscale)
{
    extern __shared__ char smem_raw[];
    const uint32_t sb = (smem_u32(smem_raw) + 255) & ~255u;

    const int tid  = threadIdx.x;
    const int wid  = tid >> 5;
    const int lane = tid & 31;

    // A loads: 2 threads/row, 2 chunks each; B loads: 4 threads/row, 1 chunk each
    const int arow = tid >> 1;
    const int ac0  = (tid & 1) * 2;
    const int brow = tid >> 2;
    const int bch  = tid & 3;
    const uint32_t sArow = (uint32_t)arow * AROW;
    const uint32_t sBrow = (uint32_t)brow * AROW;
    const __half* gA = A + (size_t)(bm + arow) * K;
    const __half* gB = B + (size_t)(bn + brow) * K;

    const int m0 = (wid >> 1) * 32;
    const int n0 = (wid & 1) * 32;

    const uint32_t aL = (uint32_t)(m0 + (lane & 15)) * AROW + (lane >> 4) * 16;
    const uint32_t bL = (uint32_t)(n0 + (lane & 7) + ((lane >> 4) & 1) * 8) * AROW
                        + ((lane >> 3) & 1) * 16;

    float acc[2][4][4];
#pragma unroll
    for (int mi = 0; mi < 2; mi++)
#pragma unroll
        for (int nj = 0; nj < 4; nj++)
#pragma unroll
            for (int k = 0; k < 4; k++) acc[mi][nj][k] = 0.f;

    const int NIT = K >> 5;

    // prologue: stages 0 and 1
#pragma unroll
    for (int st = 0; st < 2; st++) {
        const uint32_t tb = sb + st * STAGEB;
        const int k0 = st << 5;
#pragma unroll
        for (int s = 0; s < 2; s++) {
            const int ch = ac0 + s;
            cp16(tb + sArow + ch * 16, gA + k0 + ch * 8);
        }
        cp16(tb + ATILEB + sBrow + bch * 16, gB + k0 + bch * 8);
        cp_commit();
    }

    int buf = 0, nbuf = 2;
    for (int it = 0; it < NIT; it++) {
        if (it + 1 < NIT) cp_wait<1>(); else cp_wait<0>();
        __syncthreads();   // one barrier per iteration

        if (it + 2 < NIT) {
            const uint32_t tb = sb + nbuf * STAGEB;
            const int k0 = (it + 2) << 5;
#pragma unroll
            for (int s = 0; s < 2; s++) {
                const int ch = ac0 + s;
                cp16(tb + sArow + ch * 16, gA + k0 + ch * 8);
            }
            cp16(tb + ATILEB + sBrow + bch * 16, gB + k0 + bch * 8);
            cp_commit();
        }

        const uint32_t tb = sb + buf * STAGEB;

#pragma unroll
        for (int kk = 0; kk < 2; kk++) {
            uint32_t a4[2][4], b4[2][4];
#pragma unroll
            for (int mi = 0; mi < 2; mi++)
                ldsm4(a4[mi], tb + aL + mi * (16 * AROW) + kk * 32);
#pragma unroll
            for (int np = 0; np < 2; np++)
                ldsm4(b4[np], tb + ATILEB + bL + (uint32_t)np * (16 * AROW) + kk * 32);
#pragma unroll
            for (int np = 0; np < 2; np++)
#pragma unroll
                for (int mi = 0; mi < 2; mi++) {
                    mma_f16(acc[mi][2*np],     a4[mi], &b4[np][0]);
                    mma_f16(acc[mi][2*np + 1], a4[mi], &b4[np][2]);
                }
        }

        buf  = (buf == NSTAGE - 1)  ? 0 : buf + 1;
        nbuf = (nbuf == NSTAGE - 1) ? 0 : nbuf + 1;
    }

    const int g = lane >> 2, t4 = lane & 3;
#pragma unroll
    for (int mi = 0; mi < 2; mi++) {
#pragma unroll
        for (int half_ = 0; half_ < 2; half_++) {
            const int row = bm + m0 + mi * 16 + g + half_ * 8;
#pragma unroll
            for (int nj = 0; nj < 4; nj++) {
                const int col = bn + n0 + nj * 8 + 2 * t4;
                float v0 = acc[mi][nj][2 * half_]     + bias[col];
                float v1 = acc[mi][nj][2 * half_ + 1] + bias[col + 1];
                if (EPI == 1) {
                    const float2 rr = *(const float2*)&Res[(size_t)row * N + col];
                    v0 += rr.x; v1 += rr.y;
                }
                if (EPI == 2) {
                    v0 = 0.5f * v0 * (1.0f + erff(v0 * 0.70710678118654752f));
                    v1 = 0.5f * v1 * (1.0f + erff(v1 * 0.70710678118654752f));
                }
                if (EPI == 3) { v0 *= oscale; v1 *= oscale; }
                if (EPI == 2 || EPI == 3) {
                    *(__half2*)&Ch[(size_t)row * N + col] = __floats2half2_rn(v0, v1);
                } else {
                    *(float2*)&C[(size_t)row * N + col] = make_float2(v0, v1);
                }
            }
        }
    }
}

template <int EPI>
__global__ void __launch_bounds__(256, 3)
gemm_k(const __half* __restrict__ A, const __half* __restrict__ B,
       const float* __restrict__ bias, const float* __restrict__ Res,
       float* __restrict__ C, __half* __restrict__ Ch,
       int N, int K, float oscale)
{
    gemm_body<EPI>(blockIdx.y * 128, blockIdx.x * 64, A, B,
                   bias, Res, C, Ch, N, K, oscale);
}

// fused Q+V projection: grid.x = 24 (12 Q cols, 12 V cols)
__global__ void __launch_bounds__(256, 3)
gemm_qv(const __half* __restrict__ A,
        const __half* __restrict__ Wq, const __half* __restrict__ Wv,
        const float* __restrict__ bq, const float* __restrict__ bv,
        __half* __restrict__ Q, __half* __restrict__ V)
{
    const int bm = blockIdx.y * 128;
    const int xw = blockIdx.x;
    if (xw < Dm / 64)
        gemm_body<3>(bm, xw * 64, A, Wq, bq, nullptr, nullptr, Q, Dm, Dm, ATT_SCALE);
    else
        gemm_body<3>(bm, (xw - Dm / 64) * 64, A, Wv, bv, nullptr, nullptr, V, Dm, Dm, 1.0f);
}

// ---------------- tensor-core flash attention (scores = q . v), fp16 ----------------
#define AROWB 144
#define ATILE (64 * AROWB)                       // 9216
#define SMEM_ATTN_BYTES (3 * ATILE + 1024)

__global__ void __launch_bounds__(128)
attn_mma(const __half* __restrict__ Q, const __half* __restrict__ V,
         __half* __restrict__ O)
{
    extern __shared__ char smem_raw[];
    const uint32_t sb = (smem_u32(smem_raw) + 255) & ~255u;
    const uint32_t sQ = sb;
    const uint32_t sV = sb + ATILE;              // two buffers of 1 ATILE

    const int bh_ = blockIdx.y;
    const int b = bh_ / Hh, h = bh_ % Hh;
    const int l0 = blockIdx.x * 64;
    const int tid = threadIdx.x;
    const int wid = tid >> 5;
    const int lane = tid & 31;

    const int lrow = tid >> 1;
    const int cg   = (tid & 1) * 4;
    const uint32_t srow = (uint32_t)lrow * AROWB;

    const __half* gq = Q + (size_t)(b * Tt + l0 + lrow) * Dm + h * 64;

    {
#pragma unroll
        for (int s = 0; s < 4; s++) {
            const int ch = cg + s;
            cp16(sQ + srow + ch * 16, gq + ch * 8);
        }
        const __half* gv = V + (size_t)(b * Tt + 0 + lrow) * Dm + h * 64;
#pragma unroll
        for (int s = 0; s < 4; s++) {
            const int ch = cg + s;
            cp16(sV + srow + ch * 16, gv + ch * 8);
        }
        cp_commit();
    }

    uint32_t qa[4][4];
    float o[8][4];
#pragma unroll
    for (int nj = 0; nj < 8; nj++)
#pragma unroll
        for (int k = 0; k < 4; k++) o[nj][k] = 0.f;
    float mrow0 = -1e30f, mrow1 = -1e30f, ls0 = 0.f, ls1 = 0.f;

    const uint32_t aL = (uint32_t)(wid * 16 + (lane & 15)) * AROWB + (lane >> 4) * 16;
    const uint32_t bL = (uint32_t)((lane & 7) + ((lane >> 4) & 1) * 8) * AROWB
                        + ((lane >> 3) & 1) * 16;
    const uint32_t tLrow = (uint32_t)((lane & 7) + ((lane >> 3) & 1) * 8);
    const uint32_t tLcol = ((lane >> 4) & 1) * 16;

    const int NT = Tt / 64;
    for (int it = 0; it < NT; it++) {
        const int buf = it & 1;

        if (it + 1 < NT) {
            const uint32_t dst = sV + (buf ^ 1) * ATILE;
            const __half* gv = V + (size_t)(b * Tt + (it + 1) * 64 + lrow) * Dm + h * 64;
#pragma unroll
            for (int s = 0; s < 4; s++) {
                const int ch = cg + s;
                cp16(dst + srow + ch * 16, gv + ch * 8);
            }
            cp_commit();
            cp_wait<1>();
        } else {
            cp_wait<0>();
        }
        __syncthreads();

        if (it == 0) {
#pragma unroll
            for (int k = 0; k < 4; k++)
                ldsm4(qa[k], sQ + aL + k * 32);
        }

        const uint32_t vb = sV + buf * ATILE;

        float s[8][4];
#pragma unroll
        for (int nj = 0; nj < 8; nj++)
#pragma unroll
            for (int k = 0; k < 4; k++) s[nj][k] = 0.f;

#pragma unroll
        for (int kk = 0; kk < 4; kk++) {
#pragma unroll
            for (int nb = 0; nb < 4; nb++) {
                uint32_t b4[4];
                ldsm4(b4, vb + bL + (uint32_t)nb * (16 * AROWB) + kk * 32);
                mma_f16(s[2*nb],     qa[kk], &b4[0]);
                mma_f16(s[2*nb + 1], qa[kk], &b4[2]);
            }
        }

        float tmax0 = -1e30f, tmax1 = -1e30f;
#pragma unroll
        for (int nj = 0; nj < 8; nj++) {
            tmax0 = fmaxf(tmax0, fmaxf(s[nj][0], s[nj][1]));
            tmax1 = fmaxf(tmax1, fmaxf(s[nj][2], s[nj][3]));
        }
        tmax0 = fmaxf(tmax0, __shfl_xor_sync(0xffffffffu, tmax0, 1));
        tmax0 = fmaxf(tmax0, __shfl_xor_sync(0xffffffffu, tmax0, 2));
        tmax1 = fmaxf(tmax1, __shfl_xor_sync(0xffffffffu, tmax1, 1));
        tmax1 = fmaxf(tmax1, __shfl_xor_sync(0xffffffffu, tmax1, 2));

        const float mn0 = fmaxf(mrow0, tmax0), mn1 = fmaxf(mrow1, tmax1);
        const float c0 = __expf(mrow0 - mn0), c1 = __expf(mrow1 - mn1);
        mrow0 = mn0; mrow1 = mn1;

        float sum0 = 0.f, sum1 = 0.f;
#pragma unroll
        for (int nj = 0; nj < 8; nj++) {
            s[nj][0] = __expf(s[nj][0] - mn0); sum0 += s[nj][0];
            s[nj][1] = __expf(s[nj][1] - mn0); sum0 += s[nj][1];
            s[nj][2] = __expf(s[nj][2] - mn1); sum1 += s[nj][2];
            s[nj][3] = __expf(s[nj][3] - mn1); sum1 += s[nj][3];
        }
        sum0 += __shfl_xor_sync(0xffffffffu, sum0, 1);
        sum0 += __shfl_xor_sync(0xffffffffu, sum0, 2);
        sum1 += __shfl_xor_sync(0xffffffffu, sum1, 1);
        sum1 += __shfl_xor_sync(0xffffffffu, sum1, 2);
        ls0 = ls0 * c0 + sum0;
        ls1 = ls1 * c1 + sum1;

#pragma unroll
        for (int nj = 0; nj < 8; nj++) {
            o[nj][0] *= c0; o[nj][1] *= c0;
            o[nj][2] *= c1; o[nj][3] *= c1;
        }

        // pack P into fp16 A-fragments
        uint32_t pa[4][4];
#pragma unroll
        for (int kb = 0; kb < 4; kb++) {
            const int f0 = 2 * kb, f1 = 2 * kb + 1;
            pa[kb][0] = packh2(s[f0][0], s[f0][1]);
            pa[kb][1] = packh2(s[f0][2], s[f0][3]);
            pa[kb][2] = packh2(s[f1][0], s[f1][1]);
            pa[kb][3] = packh2(s[f1][2], s[f1][3]);
        }

        // O += P . V (k = t via ldmatrix.trans)
#pragma unroll
        for (int kb = 0; kb < 4; kb++) {
#pragma unroll
            for (int nb = 0; nb < 4; nb++) {
                const uint32_t ta = (uint32_t)(kb * 16 + tLrow) * AROWB
                                    + (uint32_t)nb * 32 + tLcol;
                uint32_t tv[4];
                ldsm4t(tv, vb + ta);
                mma_f16(o[2*nb],     pa[kb], &tv[0]);
                mma_f16(o[2*nb + 1], pa[kb], &tv[2]);
            }
        }
        __syncthreads();
    }

    const float inv0 = 1.f / ls0, inv1 = 1.f / ls1;
    const int g = lane >> 2, t4 = lane & 3;
    const int row0 = b * Tt + l0 + wid * 16 + g;
    const int row1 = row0 + 8;
#pragma unroll
    for (int nj = 0; nj < 8; nj++) {
        const int col = h * 64 + nj * 8 + 2 * t4;
        *(__half2*)&O[(size_t)row0 * Dm + col] =
            __floats2half2_rn(o[nj][0] * inv0, o[nj][1] * inv0);
        *(__half2*)&O[(size_t)row1 * Dm + col] =
            __floats2half2_rn(o[nj][2] * inv1, o[nj][3] * inv1);
    }
}

// ---------------- host ----------------
extern "C" void kernel_launch(void* const* d_in, const int* in_sizes, int n_in,
                              void* d_out, int out_size)
{
    const float* x     = (const float*)d_in[0];
    const float* ln1_g = (const float*)d_in[1];
    const float* ln1_b = (const float*)d_in[2];
    const float* Wq    = (const float*)d_in[3];
    const float* bq    = (const float*)d_in[4];
    const float* Wv    = (const float*)d_in[5];
    const float* bv    = (const float*)d_in[6];
    const float* Wo    = (const float*)d_in[7];
    const float* bo    = (const float*)d_in[8];
    const float* ln2_g = (const float*)d_in[9];
    const float* ln2_b = (const float*)d_in[10];
    const float* W1    = (const float*)d_in[11];
    const float* b1    = (const float*)d_in[12];
    const float* W2    = (const float*)d_in[13];
    const float* b2    = (const float*)d_in[14];
    float* out = (float*)d_out;

    float *gx, *gskip;
    __half *hh, *qh, *vh, *cxh, *ffh;
    __half *wq, *wv, *wo, *w1, *w2;
    cudaGetSymbolAddress((void**)&gx,    g_x);
    cudaGetSymbolAddress((void**)&gskip, g_skip);
    cudaGetSymbolAddress((void**)&hh,  g_h);
    cudaGetSymbolAddress((void**)&qh,  g_q);
    cudaGetSymbolAddress((void**)&vh,  g_v);
    cudaGetSymbolAddress((void**)&cxh, g_cx);
    cudaGetSymbolAddress((void**)&ffh, g_ff);
    cudaGetSymbolAddress((void**)&wq,  g_wq);
    cudaGetSymbolAddress((void**)&wv,  g_wv);
    cudaGetSymbolAddress((void**)&wo,  g_wo);
    cudaGetSymbolAddress((void**)&w1,  g_w1);
    cudaGetSymbolAddress((void**)&w2,  g_w2);

    cudaFuncSetAttribute(gemm_k<1>, cudaFuncAttributeMaxDynamicSharedMemorySize, SMEM_GEMM_BYTES);
    cudaFuncSetAttribute(gemm_k<2>, cudaFuncAttributeMaxDynamicSharedMemorySize, SMEM_GEMM_BYTES);
    cudaFuncSetAttribute(gemm_qv,   cudaFuncAttributeMaxDynamicSharedMemorySize, SMEM_GEMM_BYTES);
    cudaFuncSetAttribute(attn_mma,  cudaFuncAttributeMaxDynamicSharedMemorySize, SMEM_ATTN_BYTES);

    wconv_all<<<dim3(6336, NL), dim3(32, 8)>>>(Wq, Wv, Wo, W1, W2, wq, wv, wo, w1, w2);

    const dim3 gQV(2 * Dm / 64, Mrows / 128);  // (24, 32)
    const dim3 gD (Dm / 64,     Mrows / 128);  // (12, 32)
    const dim3 gF (FFd / 64,    Mrows / 128);  // (48, 32)
    const dim3 gA (Tt / 64, Bb * Hh);          // (16, 48)

    const float* cur = x;
    for (int l = 0; l < NL; l++) {
        float* nxt = (l == NL - 1) ? out : gx;
        const size_t oDD = (size_t)l * Dm * Dm;
        const size_t oDF = (size_t)l * Dm * FFd;
        const int lD = l * Dm, lFF = l * FFd;

        ln_kernel<<<Mrows, 256>>>(cur, ln1_g + lD, ln1_b + lD, hh);
        gemm_qv<<<gQV, 256, SMEM_GEMM_BYTES>>>(hh, wq + oDD, wv + oDD,
            bq + lD, bv + lD, qh, vh);
        attn_mma<<<gA, 128, SMEM_ATTN_BYTES>>>(qh, vh, cxh);
        gemm_k<1><<<gD, 256, SMEM_GEMM_BYTES>>>(cxh, wo + oDD,
            bo + lD, cur, gskip, nullptr, Dm, Dm, 1.0f);
        ln_kernel<<<Mrows, 256>>>(gskip, ln2_g + lD, ln2_b + lD, hh);
        gemm_k<2><<<gF, 256, SMEM_GEMM_BYTES>>>(hh, w1 + oDF,
            b1 + lFF, nullptr, nullptr, ffh, FFd, Dm, 1.0f);
        gemm_k<1><<<gD, 256, SMEM_GEMM_BYTES>>>(ffh, w2 + oDF,
            b2 + lD, gskip, nxt, nullptr, Dm, FFd, 1.0f);

        cur = nxt;
    }
}